// round 14
// baseline (speedup 1.0000x reference)
#include <cuda_runtime.h>
#include <cuda_bf16.h>
#include <cuda_fp8.h>
#include <cstdint>
#include <cstddef>

// Decoded dtypes: x[M,K] f32 (bf16-valued), w_fp4[N,K] f32, w_sf[N,K/16] f32,
// w_gs f32[1], bias[N] f32 -> out[M,N] f32 (bf16-rounded values).
#define M_DIM 8192
#define K_DIM 5120
#define N_DIM 13824

// Scratch: A = q_x*sf_x (exact bf16), B = w_fp4*w_sf (exact bf16).
__device__ uint4 g_A4[(size_t)M_DIM * K_DIM / 8];   // 83.9 MB
__device__ uint4 g_B4[(size_t)N_DIM * K_DIM / 8];   // 141.6 MB
__device__ unsigned int g_amax_bits;

// ---------------------------------------------------------------------------
__device__ __forceinline__ unsigned packbf2(float a, float b) {
    __nv_bfloat162 h = __floats2bfloat162_rn(a, b);
    return *reinterpret_cast<unsigned*>(&h);
}

// round_e2m1: searchsorted(mids, |s|, 'right') -> ties round AWAY from 0.
__device__ __forceinline__ float e2m1_round(float s) {
    float m = fminf(fabsf(s), 6.0f);
    float r;
    if (m >= 5.0f)       r = 6.0f;
    else if (m >= 3.5f)  r = 4.0f;
    else if (m >= 2.5f)  r = 3.0f;
    else if (m >= 1.75f) r = 2.0f;
    else if (m >= 1.25f) r = 1.5f;
    else if (m >= 0.75f) r = 1.0f;
    else if (m >= 0.25f) r = 0.5f;
    else                 r = 0.0f;
    return (s < 0.0f) ? -r : r;
}

// ---------------------------------------------------------------------------
// Pass 1: global amax of |x| (x is f32).
// ---------------------------------------------------------------------------
__global__ void amax_kernel(const float4* __restrict__ x, int n4) {
    float m = 0.0f;
    for (int i = blockIdx.x * blockDim.x + threadIdx.x; i < n4;
         i += gridDim.x * blockDim.x) {
        float4 v = x[i];
        m = fmaxf(m, fmaxf(fmaxf(fabsf(v.x), fabsf(v.y)),
                           fmaxf(fabsf(v.z), fabsf(v.w))));
    }
#pragma unroll
    for (int o = 16; o; o >>= 1) m = fmaxf(m, __shfl_xor_sync(0xffffffffu, m, o));
    __shared__ float sm[32];
    int lane = threadIdx.x & 31, w = threadIdx.x >> 5;
    if (lane == 0) sm[w] = m;
    __syncthreads();
    if (w == 0) {
        m = (lane < (int)(blockDim.x >> 5)) ? sm[lane] : 0.0f;
#pragma unroll
        for (int o = 16; o; o >>= 1) m = fmaxf(m, __shfl_xor_sync(0xffffffffu, m, o));
        if (lane == 0) atomicMax(&g_amax_bits, __float_as_uint(m));
    }
}

// ---------------------------------------------------------------------------
// Pass 2: NVFP4-quantize x, emit A = q*sf (exact bf16). 1 thread / 16 elems.
// ---------------------------------------------------------------------------
__global__ void quant_kernel(const float4* __restrict__ x, int nblk) {
    int t = blockIdx.x * blockDim.x + threadIdx.x;
    if (t >= nblk) return;
    float gs = 2688.0f / fmaxf(__uint_as_float(g_amax_bits), 1e-12f);

    float f[16];
#pragma unroll
    for (int i = 0; i < 4; i++) {
        float4 v = x[4 * t + i];
        f[4 * i + 0] = v.x; f[4 * i + 1] = v.y;
        f[4 * i + 2] = v.z; f[4 * i + 3] = v.w;
    }

    float am = 0.0f;
#pragma unroll
    for (int i = 0; i < 16; i++) am = fmaxf(am, fabsf(f[i]));

    float sfp = fminf((am * gs) / 6.0f, 448.0f);
    __nv_fp8_storage_t s8 = __nv_cvt_float_to_fp8(sfp, __NV_SATFINITE, __NV_E4M3);
    __half_raw hr = __nv_cvt_fp8_to_halfraw(s8, __NV_E4M3);
    float sf = __half2float(*reinterpret_cast<__half*>(&hr));

    float q[16];
    if (sf > 0.0f) {
#pragma unroll
        for (int i = 0; i < 16; i++)
            q[i] = e2m1_round((f[i] * gs) / sf) * sf;
    } else {
#pragma unroll
        for (int i = 0; i < 16; i++) q[i] = 0.0f;
    }

    uint4 o0, o1;
    o0.x = packbf2(q[0], q[1]);   o0.y = packbf2(q[2], q[3]);
    o0.z = packbf2(q[4], q[5]);   o0.w = packbf2(q[6], q[7]);
    o1.x = packbf2(q[8], q[9]);   o1.y = packbf2(q[10], q[11]);
    o1.z = packbf2(q[12], q[13]); o1.w = packbf2(q[14], q[15]);
    g_A4[2 * t] = o0;
    g_A4[2 * t + 1] = o1;
}

// ---------------------------------------------------------------------------
// Pass 3: B = w_fp4 * w_sf (exact bf16). 1 thread / 16 elems.
// ---------------------------------------------------------------------------
__global__ void bconv_kernel(const float4* __restrict__ wq,
                             const float* __restrict__ wsf, int nblk) {
    int t = blockIdx.x * blockDim.x + threadIdx.x;
    if (t >= nblk) return;
    float sf = wsf[t];
    float q[16];
#pragma unroll
    for (int i = 0; i < 4; i++) {
        float4 v = wq[4 * t + i];
        q[4 * i + 0] = v.x * sf;
        q[4 * i + 1] = v.y * sf;
        q[4 * i + 2] = v.z * sf;
        q[4 * i + 3] = v.w * sf;
    }
    uint4 o0, o1;
    o0.x = packbf2(q[0], q[1]);   o0.y = packbf2(q[2], q[3]);
    o0.z = packbf2(q[4], q[5]);   o0.w = packbf2(q[6], q[7]);
    o1.x = packbf2(q[8], q[9]);   o1.y = packbf2(q[10], q[11]);
    o1.z = packbf2(q[12], q[13]); o1.w = packbf2(q[14], q[15]);
    g_B4[2 * t] = o0;
    g_B4[2 * t + 1] = o1;
}

// ---------------------------------------------------------------------------
// Pass 4: GEMM  out = f32(bf16(A @ B^T / (x_gs*w_gs) + bias))
// 128x128x64 tile, 8 warps, mma.sync m16n8k16 bf16, XOR-swizzled SMEM,
// 3-stage cp.async pipeline. 1-D grid with SUPERTILE raster:
// bm fastest within 8-wide bn stripes -> A (84 MB) stays L2-resident,
// 8 hot B tiles per stripe; DRAM traffic ~0.7 GB instead of ~9 GB.
// ---------------------------------------------------------------------------
#define BM 128
#define BN 128
#define BK 64
#define STAGES 3
#define TILEBYTES (BM * BK * 2)
#define GRID_M (M_DIM / BM)   // 64
#define GRID_N (N_DIM / BN)   // 108
#define STRIPE 8

__device__ __forceinline__ uint32_t swz(uint32_t row, uint32_t colByte) {
    return row * 128u + (colByte ^ ((row & 7u) << 4));
}

__device__ __forceinline__ void cp16(uint32_t dst, const void* src) {
    asm volatile("cp.async.cg.shared.global [%0], [%1], 16;\n" ::"r"(dst), "l"(src));
}

__device__ __forceinline__ void ldsm4(uint32_t& r0, uint32_t& r1, uint32_t& r2,
                                      uint32_t& r3, uint32_t addr) {
    asm volatile("ldmatrix.sync.aligned.m8n8.x4.shared.b16 {%0,%1,%2,%3}, [%4];\n"
                 : "=r"(r0), "=r"(r1), "=r"(r2), "=r"(r3)
                 : "r"(addr));
}

__device__ __forceinline__ void mma16816(float* c, const uint32_t* a,
                                         const uint32_t* b) {
    asm volatile(
        "mma.sync.aligned.m16n8k16.row.col.f32.bf16.bf16.f32 "
        "{%0,%1,%2,%3}, {%4,%5,%6,%7}, {%8,%9}, {%0,%1,%2,%3};\n"
        : "+f"(c[0]), "+f"(c[1]), "+f"(c[2]), "+f"(c[3])
        : "r"(a[0]), "r"(a[1]), "r"(a[2]), "r"(a[3]), "r"(b[0]), "r"(b[1]));
}

__device__ __forceinline__ void load_stage(uint32_t sbase, int s, int kt, int bm,
                                           int bn, int lr, int lc) {
    const __nv_bfloat16* Ag = reinterpret_cast<const __nv_bfloat16*>(g_A4);
    const __nv_bfloat16* Bg = reinterpret_cast<const __nv_bfloat16*>(g_B4);
    uint32_t aS = sbase + s * TILEBYTES;
    uint32_t bS = sbase + STAGES * TILEBYTES + s * TILEBYTES;
#pragma unroll
    for (int p = 0; p < 4; p++) {
        int row = p * 32 + lr;
        cp16(aS + swz(row, lc * 16),
             Ag + (size_t)(bm * BM + row) * K_DIM + kt * BK + lc * 8);
        cp16(bS + swz(row, lc * 16),
             Bg + (size_t)(bn * BN + row) * K_DIM + kt * BK + lc * 8);
    }
}

__global__ __launch_bounds__(256) void gemm_kernel(const float* __restrict__ bias,
                                                   const float* __restrict__ w_gs,
                                                   float* __restrict__ out) {
    extern __shared__ char smem[];
    uint32_t sbase = (uint32_t)__cvta_generic_to_shared(smem);

    // Supertile raster: stripes of STRIPE bn-columns, bm varies fastest.
    const int bx = blockIdx.x;
    const int stripe_id = bx / (GRID_M * STRIPE);
    const int rem = bx - stripe_id * (GRID_M * STRIPE);
    const int bm = rem & (GRID_M - 1);          // GRID_M = 64 (pow2)
    const int bn = stripe_id * STRIPE + (rem >> 6);

    const int tid = threadIdx.x;
    const int lr = tid >> 3;
    const int lc = tid & 7;
    const int warp = tid >> 5, lane = tid & 31;
    const int wm = warp >> 2;
    const int wn = warp & 3;

    float acc[4][4][4];
#pragma unroll
    for (int i = 0; i < 4; i++)
#pragma unroll
        for (int j = 0; j < 4; j++)
#pragma unroll
            for (int k = 0; k < 4; k++) acc[i][j][k] = 0.0f;

    const int KT = K_DIM / BK;  // 80

    load_stage(sbase, 0, 0, bm, bn, lr, lc);
    asm volatile("cp.async.commit_group;\n" ::: "memory");
    load_stage(sbase, 1, 1, bm, bn, lr, lc);
    asm volatile("cp.async.commit_group;\n" ::: "memory");

    for (int kt = 0; kt < KT; kt++) {
        asm volatile("cp.async.wait_group 1;\n" ::: "memory");
        __syncthreads();

        if (kt + 2 < KT) load_stage(sbase, (kt + 2) % STAGES, kt + 2, bm, bn, lr, lc);
        asm volatile("cp.async.commit_group;\n" ::: "memory");

        uint32_t aS = sbase + (kt % STAGES) * TILEBYTES;
        uint32_t bS = sbase + STAGES * TILEBYTES + (kt % STAGES) * TILEBYTES;

#pragma unroll
        for (int ks = 0; ks < 4; ks++) {
            uint32_t a[4][4];
            uint32_t b[4][2];
#pragma unroll
            for (int i = 0; i < 4; i++) {
                int row = wm * 64 + i * 16 + (lane & 15);
                uint32_t addr = aS + swz(row, ks * 32 + ((lane >> 4) << 4));
                ldsm4(a[i][0], a[i][1], a[i][2], a[i][3], addr);
            }
#pragma unroll
            for (int j = 0; j < 2; j++) {
                int row = wn * 32 + j * 16 + ((lane >> 4) << 3) + (lane & 7);
                uint32_t addr = bS + swz(row, ks * 32 + (((lane >> 3) & 1) << 4));
                uint32_t r0, r1, r2, r3;
                ldsm4(r0, r1, r2, r3, addr);
                b[2 * j][0] = r0; b[2 * j][1] = r1;
                b[2 * j + 1][0] = r2; b[2 * j + 1][1] = r3;
            }
#pragma unroll
            for (int i = 0; i < 4; i++)
#pragma unroll
                for (int j = 0; j < 4; j++) mma16816(acc[i][j], a[i], b[j]);
        }
    }

    // Epilogue: scale 1/(x_gs*w_gs), add bias, round to bf16, store as f32.
    float amax = __uint_as_float(g_amax_bits);
    float gs = 2688.0f / fmaxf(amax, 1e-12f);
    float inv = 1.0f / (gs * w_gs[0]);

#pragma unroll
    for (int i = 0; i < 4; i++) {
        int row0 = bm * BM + wm * 64 + i * 16 + (lane >> 2);
#pragma unroll
        for (int j = 0; j < 4; j++) {
            int col = bn * BN + wn * 32 + j * 8 + ((lane & 3) << 1);
            float b0 = bias[col], b1 = bias[col + 1];
            float2 v0, v1;
            v0.x = __bfloat162float(__float2bfloat16_rn(acc[i][j][0] * inv + b0));
            v0.y = __bfloat162float(__float2bfloat16_rn(acc[i][j][1] * inv + b1));
            v1.x = __bfloat162float(__float2bfloat16_rn(acc[i][j][2] * inv + b0));
            v1.y = __bfloat162float(__float2bfloat16_rn(acc[i][j][3] * inv + b1));
            *reinterpret_cast<float2*>(out + (size_t)row0 * N_DIM + col) = v0;
            *reinterpret_cast<float2*>(out + (size_t)(row0 + 8) * N_DIM + col) = v1;
        }
    }
}

// ---------------------------------------------------------------------------
// Launch. Size-based binding (counts pairwise distinct):
//   x: M*K (f32) | w_fp4: N*K (f32) | w_sf: N*K/16 (f32) | bias: N | w_gs: 1
// amax reset via cudaMemsetAsync (memset node, capturable; one fewer launch —
// also shifts the ncu capture slot onto gemm_kernel).
// ---------------------------------------------------------------------------
extern "C" void kernel_launch(void* const* d_in, const int* in_sizes, int n_in,
                              void* d_out, int out_size) {
    const float* x = nullptr;
    const float* w_fp4 = nullptr;
    const float* w_sf = nullptr;
    const float* w_gs = nullptr;
    const float* bias = nullptr;

    for (int i = 0; i < n_in; i++) {
        long s = (long)in_sizes[i];
        if (s == (long)M_DIM * K_DIM)            x     = (const float*)d_in[i];
        else if (s == (long)N_DIM * K_DIM)       w_fp4 = (const float*)d_in[i];
        else if (s == (long)N_DIM * (K_DIM/16))  w_sf  = (const float*)d_in[i];
        else if (s == (long)N_DIM)               bias  = (const float*)d_in[i];
        else if (s == 1)                         w_gs  = (const float*)d_in[i];
    }
    if (!x)     x     = (const float*)d_in[0];
    if (!w_fp4) w_fp4 = (const float*)d_in[1];
    if (!w_sf)  w_sf  = (const float*)d_in[2];
    if (!w_gs)  w_gs  = (const float*)d_in[3];
    if (!bias)  bias  = (const float*)d_in[4];

    float* out = (float*)d_out;

    void* amax_ptr = nullptr;
    cudaGetSymbolAddress(&amax_ptr, g_amax_bits);
    cudaMemsetAsync(amax_ptr, 0, sizeof(unsigned int));

    amax_kernel<<<2048, 256>>>((const float4*)x, M_DIM * K_DIM / 4);

    int nxblk = M_DIM * K_DIM / 16;
    quant_kernel<<<(nxblk + 255) / 256, 256>>>((const float4*)x, nxblk);

    int nwblk = N_DIM * K_DIM / 16;
    bconv_kernel<<<(nwblk + 255) / 256, 256>>>((const float4*)w_fp4, w_sf, nwblk);

    cudaFuncSetAttribute(gemm_kernel, cudaFuncAttributeMaxDynamicSharedMemorySize,
                         STAGES * 2 * TILEBYTES);
    gemm_kernel<<<GRID_M * GRID_N, 256, STAGES * 2 * TILEBYTES>>>(bias, w_gs, out);
}

// round 16
// speedup vs baseline: 1.0707x; 1.0707x over previous
#include <cuda_runtime.h>
#include <cuda_bf16.h>
#include <cuda_fp8.h>
#include <cstdint>
#include <cstddef>

// Decoded dtypes: x[M,K] f32 (bf16-valued), w_fp4[N,K] f32, w_sf[N,K/16] f32,
// w_gs f32[1], bias[N] f32 -> out[M,N] f32 (bf16-rounded values).
#define M_DIM 8192
#define K_DIM 5120
#define N_DIM 13824

// Scratch: A = q_x*sf_x (exact bf16), B = w_fp4*w_sf (exact bf16).
__device__ uint4 g_A4[(size_t)M_DIM * K_DIM / 8];   // 83.9 MB
__device__ uint4 g_B4[(size_t)N_DIM * K_DIM / 8];   // 141.6 MB
__device__ unsigned int g_amax_bits;

// ---------------------------------------------------------------------------
__device__ __forceinline__ unsigned packbf2(float a, float b) {
    __nv_bfloat162 h = __floats2bfloat162_rn(a, b);
    return *reinterpret_cast<unsigned*>(&h);
}

// round_e2m1: searchsorted(mids, |s|, 'right') -> ties round AWAY from 0.
__device__ __forceinline__ float e2m1_round(float s) {
    float m = fminf(fabsf(s), 6.0f);
    float r;
    if (m >= 5.0f)       r = 6.0f;
    else if (m >= 3.5f)  r = 4.0f;
    else if (m >= 2.5f)  r = 3.0f;
    else if (m >= 1.75f) r = 2.0f;
    else if (m >= 1.25f) r = 1.5f;
    else if (m >= 0.75f) r = 1.0f;
    else if (m >= 0.25f) r = 0.5f;
    else                 r = 0.0f;
    return (s < 0.0f) ? -r : r;
}

// ---------------------------------------------------------------------------
// Pass 1: global amax of |x| (f32 input).
// ---------------------------------------------------------------------------
__global__ void amax_kernel(const float4* __restrict__ x, int n4) {
    float m = 0.0f;
    for (int i = blockIdx.x * blockDim.x + threadIdx.x; i < n4;
         i += gridDim.x * blockDim.x) {
        float4 v = x[i];
        m = fmaxf(m, fmaxf(fmaxf(fabsf(v.x), fabsf(v.y)),
                           fmaxf(fabsf(v.z), fabsf(v.w))));
    }
#pragma unroll
    for (int o = 16; o; o >>= 1) m = fmaxf(m, __shfl_xor_sync(0xffffffffu, m, o));
    __shared__ float sm[32];
    int lane = threadIdx.x & 31, w = threadIdx.x >> 5;
    if (lane == 0) sm[w] = m;
    __syncthreads();
    if (w == 0) {
        m = (lane < (int)(blockDim.x >> 5)) ? sm[lane] : 0.0f;
#pragma unroll
        for (int o = 16; o; o >>= 1) m = fmaxf(m, __shfl_xor_sync(0xffffffffu, m, o));
        if (lane == 0) atomicMax(&g_amax_bits, __float_as_uint(m));
    }
}

// ---------------------------------------------------------------------------
// Pass 2: NVFP4-quantize x, emit A = q*sf (exact bf16). 1 thread / 16 elems.
// ---------------------------------------------------------------------------
__global__ void quant_kernel(const float4* __restrict__ x, int nblk) {
    int t = blockIdx.x * blockDim.x + threadIdx.x;
    if (t >= nblk) return;
    float gs = 2688.0f / fmaxf(__uint_as_float(g_amax_bits), 1e-12f);

    float f[16];
#pragma unroll
    for (int i = 0; i < 4; i++) {
        float4 v = x[4 * t + i];
        f[4 * i + 0] = v.x; f[4 * i + 1] = v.y;
        f[4 * i + 2] = v.z; f[4 * i + 3] = v.w;
    }

    float am = 0.0f;
#pragma unroll
    for (int i = 0; i < 16; i++) am = fmaxf(am, fabsf(f[i]));

    float sfp = fminf((am * gs) / 6.0f, 448.0f);
    __nv_fp8_storage_t s8 = __nv_cvt_float_to_fp8(sfp, __NV_SATFINITE, __NV_E4M3);
    __half_raw hr = __nv_cvt_fp8_to_halfraw(s8, __NV_E4M3);
    float sf = __half2float(*reinterpret_cast<__half*>(&hr));

    float q[16];
    if (sf > 0.0f) {
#pragma unroll
        for (int i = 0; i < 16; i++)
            q[i] = e2m1_round((f[i] * gs) / sf) * sf;
    } else {
#pragma unroll
        for (int i = 0; i < 16; i++) q[i] = 0.0f;
    }

    uint4 o0, o1;
    o0.x = packbf2(q[0], q[1]);   o0.y = packbf2(q[2], q[3]);
    o0.z = packbf2(q[4], q[5]);   o0.w = packbf2(q[6], q[7]);
    o1.x = packbf2(q[8], q[9]);   o1.y = packbf2(q[10], q[11]);
    o1.z = packbf2(q[12], q[13]); o1.w = packbf2(q[14], q[15]);
    g_A4[2 * t] = o0;
    g_A4[2 * t + 1] = o1;
}

// ---------------------------------------------------------------------------
// Pass 3: B = w_fp4 * w_sf (exact bf16). 1 thread / 16 elems.
// ---------------------------------------------------------------------------
__global__ void bconv_kernel(const float4* __restrict__ wq,
                             const float* __restrict__ wsf, int nblk) {
    int t = blockIdx.x * blockDim.x + threadIdx.x;
    if (t >= nblk) return;
    float sf = wsf[t];
    float q[16];
#pragma unroll
    for (int i = 0; i < 4; i++) {
        float4 v = wq[4 * t + i];
        q[4 * i + 0] = v.x * sf;
        q[4 * i + 1] = v.y * sf;
        q[4 * i + 2] = v.z * sf;
        q[4 * i + 3] = v.w * sf;
    }
    uint4 o0, o1;
    o0.x = packbf2(q[0], q[1]);   o0.y = packbf2(q[2], q[3]);
    o0.z = packbf2(q[4], q[5]);   o0.w = packbf2(q[6], q[7]);
    o1.x = packbf2(q[8], q[9]);   o1.y = packbf2(q[10], q[11]);
    o1.z = packbf2(q[12], q[13]); o1.w = packbf2(q[14], q[15]);
    g_B4[2 * t] = o0;
    g_B4[2 * t + 1] = o1;
}

// ---------------------------------------------------------------------------
// Pass 4: GEMM  out = f32(bf16(A @ B^T / (x_gs*w_gs) + bias))
// 128x128x64 tile, 8 warps (2m x 4n), mma.sync m16n8k16 bf16, XOR-swizzled
// SMEM, 3-stage cp.async pipeline. R13 raster (bn = blockIdx.x fastest).
// NEW: carveout=100% + launch_bounds(256,2) -> 2 CTAs/SM to fill the
// per-iteration sync bubbles that capped tensor util at 71%.
// ---------------------------------------------------------------------------
#define BM 128
#define BN 128
#define BK 64
#define STAGES 3
#define TILEBYTES (BM * BK * 2)   // 16384 per operand per stage

__device__ __forceinline__ uint32_t swz(uint32_t row, uint32_t colByte) {
    return row * 128u + (colByte ^ ((row & 7u) << 4));
}

__device__ __forceinline__ void cp16(uint32_t dst, const void* src) {
    asm volatile("cp.async.cg.shared.global [%0], [%1], 16;\n" ::"r"(dst), "l"(src));
}

__device__ __forceinline__ void ldsm4(uint32_t& r0, uint32_t& r1, uint32_t& r2,
                                      uint32_t& r3, uint32_t addr) {
    asm volatile("ldmatrix.sync.aligned.m8n8.x4.shared.b16 {%0,%1,%2,%3}, [%4];\n"
                 : "=r"(r0), "=r"(r1), "=r"(r2), "=r"(r3)
                 : "r"(addr));
}

__device__ __forceinline__ void mma16816(float* c, const uint32_t* a,
                                         const uint32_t* b) {
    asm volatile(
        "mma.sync.aligned.m16n8k16.row.col.f32.bf16.bf16.f32 "
        "{%0,%1,%2,%3}, {%4,%5,%6,%7}, {%8,%9}, {%0,%1,%2,%3};\n"
        : "+f"(c[0]), "+f"(c[1]), "+f"(c[2]), "+f"(c[3])
        : "r"(a[0]), "r"(a[1]), "r"(a[2]), "r"(a[3]), "r"(b[0]), "r"(b[1]));
}

__device__ __forceinline__ void load_stage(uint32_t sbase, int s, int kt, int bm,
                                           int bn, int lr, int lc) {
    const __nv_bfloat16* Ag = reinterpret_cast<const __nv_bfloat16*>(g_A4);
    const __nv_bfloat16* Bg = reinterpret_cast<const __nv_bfloat16*>(g_B4);
    uint32_t aS = sbase + s * TILEBYTES;
    uint32_t bS = sbase + STAGES * TILEBYTES + s * TILEBYTES;
#pragma unroll
    for (int p = 0; p < 4; p++) {
        int row = p * 32 + lr;
        cp16(aS + swz(row, lc * 16),
             Ag + (size_t)(bm * BM + row) * K_DIM + kt * BK + lc * 8);
        cp16(bS + swz(row, lc * 16),
             Bg + (size_t)(bn * BN + row) * K_DIM + kt * BK + lc * 8);
    }
}

__global__ __launch_bounds__(256, 2) void gemm_kernel(
    const float* __restrict__ bias, const float* __restrict__ w_gs,
    float* __restrict__ out) {
    extern __shared__ char smem[];
    uint32_t sbase = (uint32_t)__cvta_generic_to_shared(smem);

    const int tid = threadIdx.x;
    const int bn = blockIdx.x, bm = blockIdx.y;
    const int lr = tid >> 3;
    const int lc = tid & 7;
    const int warp = tid >> 5, lane = tid & 31;
    const int wm = warp >> 2;   // 0..1 -> 64-row slab
    const int wn = warp & 3;    // 0..3 -> 32-col slab

    float acc[4][4][4];
#pragma unroll
    for (int i = 0; i < 4; i++)
#pragma unroll
        for (int j = 0; j < 4; j++)
#pragma unroll
            for (int k = 0; k < 4; k++) acc[i][j][k] = 0.0f;

    const int KT = K_DIM / BK;  // 80

    load_stage(sbase, 0, 0, bm, bn, lr, lc);
    asm volatile("cp.async.commit_group;\n" ::: "memory");
    load_stage(sbase, 1, 1, bm, bn, lr, lc);
    asm volatile("cp.async.commit_group;\n" ::: "memory");

    for (int kt = 0; kt < KT; kt++) {
        asm volatile("cp.async.wait_group 1;\n" ::: "memory");
        __syncthreads();

        if (kt + 2 < KT) load_stage(sbase, (kt + 2) % STAGES, kt + 2, bm, bn, lr, lc);
        asm volatile("cp.async.commit_group;\n" ::: "memory");

        uint32_t aS = sbase + (kt % STAGES) * TILEBYTES;
        uint32_t bS = sbase + STAGES * TILEBYTES + (kt % STAGES) * TILEBYTES;

#pragma unroll
        for (int ks = 0; ks < 4; ks++) {
            uint32_t a[4][4];
            uint32_t b[4][2];
#pragma unroll
            for (int i = 0; i < 4; i++) {
                int row = wm * 64 + i * 16 + (lane & 15);
                uint32_t addr = aS + swz(row, ks * 32 + ((lane >> 4) << 4));
                ldsm4(a[i][0], a[i][1], a[i][2], a[i][3], addr);
            }
#pragma unroll
            for (int j = 0; j < 2; j++) {
                int row = wn * 32 + j * 16 + ((lane >> 4) << 3) + (lane & 7);
                uint32_t addr = bS + swz(row, ks * 32 + (((lane >> 3) & 1) << 4));
                uint32_t r0, r1, r2, r3;
                ldsm4(r0, r1, r2, r3, addr);
                b[2 * j][0] = r0; b[2 * j][1] = r1;
                b[2 * j + 1][0] = r2; b[2 * j + 1][1] = r3;
            }
#pragma unroll
            for (int i = 0; i < 4; i++)
#pragma unroll
                for (int j = 0; j < 4; j++) mma16816(acc[i][j], a[i], b[j]);
        }
    }

    // Epilogue: scale 1/(x_gs*w_gs), add bias, round to bf16, store as f32.
    float amax = __uint_as_float(g_amax_bits);
    float gs = 2688.0f / fmaxf(amax, 1e-12f);
    float inv = 1.0f / (gs * w_gs[0]);

#pragma unroll
    for (int i = 0; i < 4; i++) {
        int row0 = bm * BM + wm * 64 + i * 16 + (lane >> 2);
#pragma unroll
        for (int j = 0; j < 4; j++) {
            int col = bn * BN + wn * 32 + j * 8 + ((lane & 3) << 1);
            float b0 = bias[col], b1 = bias[col + 1];
            float2 v0, v1;
            v0.x = __bfloat162float(__float2bfloat16_rn(acc[i][j][0] * inv + b0));
            v0.y = __bfloat162float(__float2bfloat16_rn(acc[i][j][1] * inv + b1));
            v1.x = __bfloat162float(__float2bfloat16_rn(acc[i][j][2] * inv + b0));
            v1.y = __bfloat162float(__float2bfloat16_rn(acc[i][j][3] * inv + b1));
            *reinterpret_cast<float2*>(out + (size_t)row0 * N_DIM + col) = v0;
            *reinterpret_cast<float2*>(out + (size_t)(row0 + 8) * N_DIM + col) = v1;
        }
    }
}

// ---------------------------------------------------------------------------
// Launch. Size-based binding (counts pairwise distinct):
//   x: M*K (f32) | w_fp4: N*K (f32) | w_sf: N*K/16 (f32) | bias: N | w_gs: 1
// ---------------------------------------------------------------------------
extern "C" void kernel_launch(void* const* d_in, const int* in_sizes, int n_in,
                              void* d_out, int out_size) {
    const float* x = nullptr;
    const float* w_fp4 = nullptr;
    const float* w_sf = nullptr;
    const float* w_gs = nullptr;
    const float* bias = nullptr;

    for (int i = 0; i < n_in; i++) {
        long s = (long)in_sizes[i];
        if (s == (long)M_DIM * K_DIM)            x     = (const float*)d_in[i];
        else if (s == (long)N_DIM * K_DIM)       w_fp4 = (const float*)d_in[i];
        else if (s == (long)N_DIM * (K_DIM/16))  w_sf  = (const float*)d_in[i];
        else if (s == (long)N_DIM)               bias  = (const float*)d_in[i];
        else if (s == 1)                         w_gs  = (const float*)d_in[i];
    }
    if (!x)     x     = (const float*)d_in[0];
    if (!w_fp4) w_fp4 = (const float*)d_in[1];
    if (!w_sf)  w_sf  = (const float*)d_in[2];
    if (!w_gs)  w_gs  = (const float*)d_in[3];
    if (!bias)  bias  = (const float*)d_in[4];

    float* out = (float*)d_out;

    void* amax_ptr = nullptr;
    cudaGetSymbolAddress(&amax_ptr, g_amax_bits);
    cudaMemsetAsync(amax_ptr, 0, sizeof(unsigned int));

    amax_kernel<<<2048, 256>>>((const float4*)x, M_DIM * K_DIM / 4);

    int nxblk = M_DIM * K_DIM / 16;
    quant_kernel<<<(nxblk + 255) / 256, 256>>>((const float4*)x, nxblk);

    int nwblk = N_DIM * K_DIM / 16;
    bconv_kernel<<<(nwblk + 255) / 256, 256>>>((const float4*)w_fp4, w_sf, nwblk);

    cudaFuncSetAttribute(gemm_kernel, cudaFuncAttributeMaxDynamicSharedMemorySize,
                         STAGES * 2 * TILEBYTES);
    cudaFuncSetAttribute(gemm_kernel,
                         cudaFuncAttributePreferredSharedMemoryCarveout, 100);
    dim3 grid(N_DIM / BN, M_DIM / BM);  // R13 raster: bn fastest
    gemm_kernel<<<grid, 256, STAGES * 2 * TILEBYTES>>>(bias, w_gs, out);
}